// round 8
// baseline (speedup 1.0000x reference)
#include <cuda_runtime.h>
#include <cuda_bf16.h>
#include <cstdint>

#define HIDDEN 3584
#define RDIM   224

// ---------------- scratch (static device allocations) ----------------
__device__ __nv_bfloat16 g_wdp[RDIM * HIDDEN];     // gamma * w_down, bf16  [224][3584]
__device__ __nv_bfloat16 g_wup[HIDDEN * RDIM];     // w_up bf16             [3584][224]
__device__ float         g_c1[RDIM];
__device__ float         g_c2[RDIM];

// ---------------- helpers ----------------
__device__ __forceinline__ uint32_t smem_u32(const void* p) {
    uint32_t a;
    asm("{ .reg .u64 t; cvta.to.shared.u64 t, %1; cvt.u32.u64 %0, t; }" : "=r"(a) : "l"(p));
    return a;
}

__device__ __forceinline__ void mma_bf16(float c[4], const uint32_t a[4],
                                         uint32_t b0, uint32_t b1) {
    asm volatile(
        "mma.sync.aligned.m16n8k16.row.col.f32.bf16.bf16.f32 "
        "{%0,%1,%2,%3}, {%4,%5,%6,%7}, {%8,%9}, {%0,%1,%2,%3};\n"
        : "+f"(c[0]), "+f"(c[1]), "+f"(c[2]), "+f"(c[3])
        : "r"(a[0]), "r"(a[1]), "r"(a[2]), "r"(a[3]), "r"(b0), "r"(b1));
}

__device__ __forceinline__ void ldsm_x4(uint32_t* r, uint32_t addr) {
    asm volatile("ldmatrix.sync.aligned.m8n8.x4.shared.b16 {%0,%1,%2,%3}, [%4];"
                 : "=r"(r[0]), "=r"(r[1]), "=r"(r[2]), "=r"(r[3]) : "r"(addr));
}
__device__ __forceinline__ void ldsm_x2(uint32_t* r, uint32_t addr) {
    asm volatile("ldmatrix.sync.aligned.m8n8.x2.shared.b16 {%0,%1}, [%2];"
                 : "=r"(r[0]), "=r"(r[1]) : "r"(addr));
}

__device__ __forceinline__ float gelu_exact(float y) {
    return 0.5f * y * (1.0f + erff(y * 0.70710678118654752f));
}

__device__ __forceinline__ void cp16(void* dst_smem, const void* src_gmem) {
    uint32_t d = (uint32_t)__cvta_generic_to_shared(dst_smem);
    asm volatile("cp.async.cg.shared.global [%0], [%1], 16;\n" :: "r"(d), "l"(src_gmem));
}
#define CP_COMMIT() asm volatile("cp.async.commit_group;\n" ::: "memory")
#define CP_WAIT0()  asm volatile("cp.async.wait_group 0;\n" ::: "memory")

// ---------------- prep kernels ----------------
__global__ void prep_down(const float* __restrict__ wd, const float* __restrict__ gamma,
                          const float* __restrict__ beta) {
    int r = blockIdx.x;
    const float* row = wd + (size_t)r * HIDDEN;
    float c1 = 0.f, c2 = 0.f;
    for (int h = threadIdx.x; h < HIDDEN; h += 256) {
        float g = gamma[h], w = row[h];
        g_wdp[(size_t)r * HIDDEN + h] = __float2bfloat16(g * w);
        c1 += g * w;
        c2 += beta[h] * w;
    }
    __shared__ float s1[256], s2[256];
    s1[threadIdx.x] = c1; s2[threadIdx.x] = c2;
    __syncthreads();
    for (int o = 128; o > 0; o >>= 1) {
        if ((int)threadIdx.x < o) {
            s1[threadIdx.x] += s1[threadIdx.x + o];
            s2[threadIdx.x] += s2[threadIdx.x + o];
        }
        __syncthreads();
    }
    if (threadIdx.x == 0) { g_c1[r] = s1[0]; g_c2[r] = s2[0]; }
}

__global__ void prep_up(const float* __restrict__ wu) {
    int i = blockIdx.x * blockDim.x + threadIdx.x;
    if (i < HIDDEN * RDIM) g_wup[i] = __float2bfloat16(wu[i]);
}

// ---------------- fused kernel: LN + down + GELU + up + residual ----------------
// One CTA = 128 tokens, 512 threads (16 warps). Phase 1: down-GEMM (K=3584,
// 64-chunk double-buffer), LN applied analytically, GELU -> mid in SMEM.
// Phase 2: 28 chunks of 128 w_up cols, double-buffered; out = x + alpha*mid@w_up^T.
#define K1_AS 72
#define K1_ABUF (128 * K1_AS)                 // halves
#define K1_BBUF (RDIM * K1_AS)
#define K1_NCH  (HIDDEN / 64)                 // 56
#define MID_AS 232
#define MID_SZ (128 * MID_AS)                 // 29696 halves
#define W_BUF  (128 * MID_AS)                 // phase-2 w_up chunk buffer (halves)

__global__ __launch_bounds__(512, 1)
void kernel_fused(const float* __restrict__ x, const float* __restrict__ alpha_p,
                  float* __restrict__ out) {
    extern __shared__ __nv_bfloat16 sm[];
    __nv_bfloat16* sMid = sm;                  // [128][MID_AS]
    __nv_bfloat16* sP   = sm + MID_SZ;         // phase1: A|B bufs; phase2: w bufs
    __nv_bfloat16* sA   = sP;                  // 2 x [128][K1_AS]
    __nv_bfloat16* sB   = sP + 2 * K1_ABUF;    // 2 x [224][K1_AS]

    __shared__ float sS1[128][4];
    __shared__ float sS2[128][4];
    __shared__ float sMu[128], sRstd[128];
    __shared__ float sC1[RDIM], sC2[RDIM];

    const int tid  = threadIdx.x;
    const int warp = tid >> 5, lane = tid & 31;
    const int gid  = lane >> 2, tig = lane & 3;
    const int wm   = warp >> 2, wn = warp & 3;   // 4(m) x 4(n)
    const int m0   = blockIdx.x * 128;

    for (int i = tid; i < RDIM; i += 512) { sC1[i] = g_c1[i]; sC2[i] = g_c2[i]; }

    // ================= PHASE 1: LN + down-proj + GELU -> sMid =================
    const uint32_t aU = smem_u32(sA), bU = smem_u32(sB);
    const uint32_t aLane =
        ((uint32_t)((wm * 32 + (lane & 7) + ((lane >> 3) & 1) * 8) * K1_AS
                    + (lane >> 4) * 8)) * 2u;
    uint32_t bPair[4];
    {
        const int kc = ((lane >> 3) & 1) * 8;
#pragma unroll
        for (int p = 0; p < 3; p++) {
            int nr = wn * 56 + p * 16 + (lane & 7) + ((lane >> 4) & 1) * 8;
            bPair[p] = (uint32_t)(nr * K1_AS + kc) * 2u;
        }
        int nr3 = wn * 56 + 48 + (lane & 7);
        bPair[3] = (uint32_t)(nr3 * K1_AS + kc) * 2u;
    }

    float acc[2][7][4];
#pragma unroll
    for (int a = 0; a < 2; a++)
#pragma unroll
        for (int b = 0; b < 7; b++)
#pragma unroll
            for (int c = 0; c < 4; c++) acc[a][b][c] = 0.f;

    const int rowx = tid >> 2, lq = tid & 3;     // A loader: 4 threads/row
    const float* xr = x + (size_t)(m0 + rowx) * HIDDEN + lq * 16;
    const int brow = tid >> 3, bc8 = tid & 7;
    float s1 = 0.f, s2 = 0.f;

#define K1_FILL_B(buf, ko) do {                                                 \
    _Pragma("unroll")                                                           \
    for (int j = 0; j < 4; j++) {                                               \
        int row_ = brow + j * 64;                                               \
        if (row_ < RDIM)                                                        \
            cp16(&sB[(buf) * K1_BBUF + row_ * K1_AS + bc8 * 8],                 \
                 g_wdp + (size_t)row_ * HIDDEN + (ko) + bc8 * 8);               \
    } } while (0)

#define K1_LOAD_X(ko, v) do {                                                   \
    _Pragma("unroll")                                                           \
    for (int i = 0; i < 4; i++) (v)[i] = *(const float4*)(xr + (ko) + i * 4);   \
    } while (0)

#define K1_STORE_A(buf, v) do {                                                 \
    _Pragma("unroll")                                                           \
    for (int i = 0; i < 4; i++) {                                               \
        s1 += (v)[i].x + (v)[i].y + (v)[i].z + (v)[i].w;                        \
        s2 += (v)[i].x*(v)[i].x + (v)[i].y*(v)[i].y                             \
            + (v)[i].z*(v)[i].z + (v)[i].w*(v)[i].w;                            \
    }                                                                           \
    {                                                                           \
        uint4 pk;                                                               \
        __nv_bfloat162 t0 = __floats2bfloat162_rn((v)[0].x, (v)[0].y);          \
        __nv_bfloat162 t1 = __floats2bfloat162_rn((v)[0].z, (v)[0].w);          \
        __nv_bfloat162 t2 = __floats2bfloat162_rn((v)[1].x, (v)[1].y);          \
        __nv_bfloat162 t3 = __floats2bfloat162_rn((v)[1].z, (v)[1].w);          \
        pk.x = *(uint32_t*)&t0; pk.y = *(uint32_t*)&t1;                         \
        pk.z = *(uint32_t*)&t2; pk.w = *(uint32_t*)&t3;                         \
        *(uint4*)&sA[(buf) * K1_ABUF + rowx * K1_AS + lq * 16] = pk;            \
        __nv_bfloat162 u0 = __floats2bfloat162_rn((v)[2].x, (v)[2].y);          \
        __nv_bfloat162 u1 = __floats2bfloat162_rn((v)[2].z, (v)[2].w);          \
        __nv_bfloat162 u2 = __floats2bfloat162_rn((v)[3].x, (v)[3].y);          \
        __nv_bfloat162 u3 = __floats2bfloat162_rn((v)[3].z, (v)[3].w);          \
        pk.x = *(uint32_t*)&u0; pk.y = *(uint32_t*)&u1;                         \
        pk.z = *(uint32_t*)&u2; pk.w = *(uint32_t*)&u3;                         \
        *(uint4*)&sA[(buf) * K1_ABUF + rowx * K1_AS + lq * 16 + 8] = pk;        \
    } } while (0)

    // ---- prologue ----
    K1_FILL_B(0, 0);
    CP_COMMIT();
    {
        float4 v[4];
        K1_LOAD_X(0, v);
        K1_STORE_A(0, v);
    }
    CP_WAIT0();
    __syncthreads();

    // ---- phase-1 main loop ----
    for (int it = 0; it < K1_NCH; it++) {
        const int cur = it & 1, nxt = cur ^ 1;
        const uint32_t aCur = aU + (uint32_t)cur * (K1_ABUF * 2);
        const uint32_t bCur = bU + (uint32_t)cur * (K1_BBUF * 2);

        float4 v[4];
        if (it < K1_NCH - 1) {
            const int ko = (it + 1) * 64;
            K1_FILL_B(nxt, ko);
            CP_COMMIT();
            K1_LOAD_X(ko, v);
        }

#pragma unroll
        for (int ks = 0; ks < 4; ks++) {
            const uint32_t kOff = (uint32_t)ks * 32u;
            uint32_t a0[4], a1[4];
            ldsm_x4(a0, aCur + aLane + kOff);
            ldsm_x4(a1, aCur + aLane + (uint32_t)(16 * K1_AS * 2) + kOff);
            uint32_t bf[14];
            ldsm_x4(&bf[0],  bCur + bPair[0] + kOff);
            ldsm_x4(&bf[4],  bCur + bPair[1] + kOff);
            ldsm_x4(&bf[8],  bCur + bPair[2] + kOff);
            ldsm_x2(&bf[12], bCur + bPair[3] + kOff);
#pragma unroll
            for (int nt = 0; nt < 7; nt++) {
                mma_bf16(acc[0][nt], a0, bf[2 * nt], bf[2 * nt + 1]);
                mma_bf16(acc[1][nt], a1, bf[2 * nt], bf[2 * nt + 1]);
            }
        }

        if (it < K1_NCH - 1) {
            K1_STORE_A(nxt, v);
            CP_WAIT0();
            __syncthreads();
        }
    }

    // ---- row stats (syncs all warps after last MMA) ----
    sS1[rowx][lq] = s1; sS2[rowx][lq] = s2;
    __syncthreads();
    if (tid < 128) {
        float t1 = sS1[tid][0] + sS1[tid][1] + sS1[tid][2] + sS1[tid][3];
        float t2 = sS2[tid][0] + sS2[tid][1] + sS2[tid][2] + sS2[tid][3];
        float mu = t1 * (1.0f / HIDDEN);
        float var = t2 * (1.0f / HIDDEN) - mu * mu;
        sMu[tid] = mu;
        sRstd[tid] = rsqrtf(var + 1e-5f);
    }
    __syncthreads();

    // ---- issue w_up chunk-0 load (phase-1 buffers are dead now) ----
#define LOAD_W(buf, j_) do {                                                    \
    const int nr0 = (j_) * 128;                                                 \
    _Pragma("unroll")                                                           \
    for (int j = 0; j < 7; j++) {                                               \
        int idx = tid + j * 512;                                                \
        int row_ = idx / 28, c_ = idx % 28;                                     \
        cp16(&sP[(buf) * W_BUF + row_ * MID_AS + c_ * 8],                       \
             g_wup + (size_t)(nr0 + row_) * RDIM + c_ * 8);                     \
    } } while (0)

    LOAD_W(0, 0);
    CP_COMMIT();

    // ---- phase-1 epilogue: LN correction + GELU -> sMid (overlaps w_up load) ----
#pragma unroll
    for (int mt = 0; mt < 2; mt++) {
        const int r0 = wm * 32 + mt * 16 + gid;
        const float mu0 = sMu[r0],     rs0 = sRstd[r0];
        const float mu1 = sMu[r0 + 8], rs1 = sRstd[r0 + 8];
#pragma unroll
        for (int nt = 0; nt < 7; nt++) {
            const int c = wn * 56 + nt * 8 + tig * 2;
            const float c1a = sC1[c], c1b = sC1[c + 1];
            const float c2a = sC2[c], c2b = sC2[c + 1];
            float y00 = rs0 * (acc[mt][nt][0] - mu0 * c1a) + c2a;
            float y01 = rs0 * (acc[mt][nt][1] - mu0 * c1b) + c2b;
            float y10 = rs1 * (acc[mt][nt][2] - mu1 * c1a) + c2a;
            float y11 = rs1 * (acc[mt][nt][3] - mu1 * c1b) + c2b;
            *(__nv_bfloat162*)&sMid[r0 * MID_AS + c] =
                __floats2bfloat162_rn(gelu_exact(y00), gelu_exact(y01));
            *(__nv_bfloat162*)&sMid[(r0 + 8) * MID_AS + c] =
                __floats2bfloat162_rn(gelu_exact(y10), gelu_exact(y11));
        }
    }
    CP_WAIT0();
    __syncthreads();

    // ================= PHASE 2: up-proj + residual =================
    const float alpha = __ldg(alpha_p);
    const uint32_t midU = smem_u32(sMid), wU = smem_u32(sP);
    const uint32_t aLane2 =
        ((uint32_t)((wm * 32 + (lane & 7) + ((lane >> 3) & 1) * 8) * MID_AS
                    + (lane >> 4) * 8)) * 2u;
    const uint32_t bLane2 =
        ((uint32_t)((wn * 32 + (lane & 7) + ((lane >> 4) & 1) * 8) * MID_AS
                    + ((lane >> 3) & 1) * 8)) * 2u;

    for (int j = 0; j < 28; j++) {
        const int cur = j & 1, nxt = cur ^ 1;
        const int nc0 = j * 128;
        const uint32_t wCur = wU + (uint32_t)cur * (W_BUF * 2);

        // prefetch epilogue x into registers (hidden under MMAs)
        float2 xv[2][4][2];
#pragma unroll
        for (int mt = 0; mt < 2; mt++) {
            const int r0 = m0 + wm * 32 + mt * 16 + gid;
#pragma unroll
            for (int nt = 0; nt < 4; nt++) {
                const int c = nc0 + wn * 32 + nt * 8 + tig * 2;
                const size_t i0 = (size_t)r0 * HIDDEN + c;
                xv[mt][nt][0] = *(const float2*)(x + i0);
                xv[mt][nt][1] = *(const float2*)(x + i0 + (size_t)8 * HIDDEN);
            }
        }

        if (j < 27) {
            LOAD_W(nxt, j + 1);
            CP_COMMIT();
        }

        float acc2[2][4][4];
#pragma unroll
        for (int a = 0; a < 2; a++)
#pragma unroll
            for (int b = 0; b < 4; b++)
#pragma unroll
                for (int c = 0; c < 4; c++) acc2[a][b][c] = 0.f;

#pragma unroll
        for (int ks = 0; ks < 14; ks++) {
            const uint32_t kOff = (uint32_t)ks * 32u;
            uint32_t a0[4], a1[4], bf[2][4];
            ldsm_x4(a0, midU + aLane2 + kOff);
            ldsm_x4(a1, midU + aLane2 + (uint32_t)(16 * MID_AS * 2) + kOff);
            ldsm_x4(bf[0], wCur + bLane2 + kOff);
            ldsm_x4(bf[1], wCur + bLane2 + (uint32_t)(16 * MID_AS * 2) + kOff);
            mma_bf16(acc2[0][0], a0, bf[0][0], bf[0][1]);
            mma_bf16(acc2[0][1], a0, bf[0][2], bf[0][3]);
            mma_bf16(acc2[0][2], a0, bf[1][0], bf[1][1]);
            mma_bf16(acc2[0][3], a0, bf[1][2], bf[1][3]);
            mma_bf16(acc2[1][0], a1, bf[0][0], bf[0][1]);
            mma_bf16(acc2[1][1], a1, bf[0][2], bf[0][3]);
            mma_bf16(acc2[1][2], a1, bf[1][0], bf[1][1]);
            mma_bf16(acc2[1][3], a1, bf[1][2], bf[1][3]);
        }

        // epilogue: residual add + store (x already in regs)
#pragma unroll
        for (int mt = 0; mt < 2; mt++) {
            const int r0 = m0 + wm * 32 + mt * 16 + gid;
#pragma unroll
            for (int nt = 0; nt < 4; nt++) {
                const int c = nc0 + wn * 32 + nt * 8 + tig * 2;
                const size_t i0 = (size_t)r0 * HIDDEN + c;
                const size_t i1 = i0 + (size_t)8 * HIDDEN;
                float2 o0, o1;
                o0.x = xv[mt][nt][0].x + alpha * acc2[mt][nt][0];
                o0.y = xv[mt][nt][0].y + alpha * acc2[mt][nt][1];
                o1.x = xv[mt][nt][1].x + alpha * acc2[mt][nt][2];
                o1.y = xv[mt][nt][1].y + alpha * acc2[mt][nt][3];
                *(float2*)(out + i0) = o0;
                *(float2*)(out + i1) = o1;
            }
        }

        if (j < 27) {
            CP_WAIT0();
            __syncthreads();
        }
    }
#undef K1_FILL_B
#undef K1_LOAD_X
#undef K1_STORE_A
#undef LOAD_W
}

// ---------------- launch ----------------
extern "C" void kernel_launch(void* const* d_in, const int* in_sizes, int n_in,
                              void* d_out, int out_size) {
    const float* x     = (const float*)d_in[0];
    const float* gamma = (const float*)d_in[1];
    const float* beta  = (const float*)d_in[2];
    const float* wd    = (const float*)d_in[3];
    const float* wu    = (const float*)d_in[4];
    const float* alpha = (const float*)d_in[5];
    const int tokens = in_sizes[0] / HIDDEN;   // 16384

    prep_down<<<RDIM, 256>>>(wd, gamma, beta);
    prep_up<<<(HIDDEN * RDIM + 255) / 256, 256>>>(wu);

    // smem: mid (29696) + max(phase1 50688, phase2 2*29696=59392) halves
    const int smem = (MID_SZ + 2 * W_BUF) * (int)sizeof(__nv_bfloat16);  // 178176
    cudaFuncSetAttribute(kernel_fused, cudaFuncAttributeMaxDynamicSharedMemorySize, smem);
    kernel_fused<<<tokens / 128, 512, smem>>>(x, alpha, (float*)d_out);
}